// round 14
// baseline (speedup 1.0000x reference)
#include <cuda_runtime.h>
#include <cuda_bf16.h>
#include <stdint.h>
#include <math.h>

#define BATCH 32
#define CH    512
#define NTOK  1024
#define NGRP  32
#define CPG   16

typedef __nv_bfloat16 bf16;
typedef unsigned int u32;

// ---------------- scratch (device globals) ----------------
__device__ bf16  g_h  [(size_t)BATCH * NTOK * CH];       // [b][t][c]
__device__ bf16  g_qk [(size_t)BATCH * NTOK * 2 * CH];   // [b][t][q|k]
__device__ bf16  g_vt [(size_t)BATCH * CH * NTOK];       // [b][c][t]
__device__ bf16  g_s  [(size_t)BATCH * NTOK * NTOK];     // scores bf16
__device__ bf16  g_p  [(size_t)BATCH * NTOK * NTOK];     // probs bf16
__device__ bf16  g_o  [(size_t)BATCH * NTOK * CH];       // [b][t][c]
__device__ bf16  g_w  [4 * CH * CH];                     // wq|wk|wv|wp bf16
__device__ float g_bqk[2 * CH];                          // bq|bk

// ---------------- weight fp32 -> bf16 (+ fused qk bias) ----------------
__global__ void convw_kernel(const float* __restrict__ wq, const float* __restrict__ wk,
                             const float* __restrict__ wv, const float* __restrict__ wp,
                             const float* __restrict__ bq, const float* __restrict__ bk,
                             bf16* __restrict__ w, float* __restrict__ bqk) {
    int i = blockIdx.x * 256 + threadIdx.x;
    if (i < CH * CH) {
        w[i]               = __float2bfloat16(wq[i]);
        w[CH * CH + i]     = __float2bfloat16(wk[i]);
        w[2 * CH * CH + i] = __float2bfloat16(wv[i]);
        w[3 * CH * CH + i] = __float2bfloat16(wp[i]);
    }
    if (i < CH) {
        bqk[i]      = bq[i];
        bqk[CH + i] = bk[i];
    }
}

// ---------------- GroupNorm: single pass, fp32 stats, bf16 out --------------
__global__ void __launch_bounds__(256)
gn_kernel(const float* __restrict__ x,
          const float* __restrict__ gw,
          const float* __restrict__ gb,
          bf16* __restrict__ h) {
    const int bg = blockIdx.x;
    const int b = bg / NGRP, g = bg % NGRP;
    const int n = CPG * NTOK;
    const size_t base = (size_t)bg * n;
    const int t = threadIdx.x;

    float v[4][CPG];
    float s = 0.f, ss = 0.f;
    #pragma unroll
    for (int j = 0; j < 4; j++) {
        const int tok = t + 256 * j;
        #pragma unroll
        for (int i = 0; i < CPG; i++) {
            float val = x[base + (size_t)i * NTOK + tok];
            v[j][i] = val; s += val; ss += val * val;
        }
    }
    __shared__ float rs[256], rq[256];
    rs[t] = s; rq[t] = ss;
    __syncthreads();
    for (int o = 128; o > 0; o >>= 1) {
        if (t < o) { rs[t] += rs[t + o]; rq[t] += rq[t + o]; }
        __syncthreads();
    }
    const float mean = rs[0] * (1.0f / n);
    const float var  = rq[0] * (1.0f / n) - mean * mean;
    const float rstd = rsqrtf(var + 1e-5f);

    float a[CPG], c[CPG];
    #pragma unroll
    for (int i = 0; i < CPG; i++) {
        a[i] = rstd * gw[g * CPG + i];
        c[i] = gb[g * CPG + i] - mean * a[i];
    }
    #pragma unroll
    for (int j = 0; j < 4; j++) {
        const int tok = t + 256 * j;
        bf16 buf[CPG];
        #pragma unroll
        for (int i = 0; i < CPG; i++)
            buf[i] = __float2bfloat16(v[j][i] * a[i] + c[i]);
        size_t ho = ((size_t)(b * NTOK + tok)) * CH + g * CPG;
        uint4* dst = reinterpret_cast<uint4*>(&h[ho]);
        const uint4* src = reinterpret_cast<const uint4*>(buf);
        dst[0] = src[0];
        dst[1] = src[1];
    }
}

// ---------------- epilogue store helpers ----------------
__device__ __forceinline__ void store2(float* p, float v0, float v1) {
    *reinterpret_cast<float2*>(p) = make_float2(v0, v1);
}
__device__ __forceinline__ void store2(bf16* p, float v0, float v1) {
    *reinterpret_cast<__nv_bfloat162*>(p) = __floats2bfloat162_rn(v0, v1);
}

// ---------------- bf16 TN GEMM: 128x128 tile, 128 thr, 64x64 warp tile ------
// C[m][n] = alpha * sum_k A[m][k]*B[n][k] (+bias_m[m]) (+bias_n[n]) (+resid)
// A rows at lda, B rows at ldb (elements); C: [M][N] (ld=N).
// BK=64, 3-stage cp.async ring, early issue, one __syncthreads per k-tile.
#define BM 128
#define BN 128
#define BK 64
#define LDSW 72  // BK + 8 pad (conflict-free ldmatrix)
#define NSTG 3
#define NTHR 128
#define GEMM_SMEM ((BM + BN) * LDSW * NSTG * 2)   // 110592 bytes

template<typename OutT>
__global__ void __launch_bounds__(NTHR, 2)
mma_gemm(const bf16* __restrict__ A, const bf16* __restrict__ B, OutT* __restrict__ C,
         int K, int lda, int ldb, int N, long sA, long sB, long sC,
         float alpha, const float* __restrict__ bias_m, const float* __restrict__ bias_n,
         const float* __restrict__ resid, long sR) {
    extern __shared__ bf16 sm[];
    bf16* Asm = sm;
    bf16* Bsm = sm + NSTG * BM * LDSW;

    const int bz = blockIdx.z;
    const bf16* Ab = A + (size_t)bz * sA + (size_t)(blockIdx.y * BM) * lda;
    const bf16* Bb = B + (size_t)bz * sB + (size_t)(blockIdx.x * BN) * ldb;

    const int t = threadIdx.x;
    const int lane = t & 31, w = t >> 5;             // 4 warps
    const int wm = (w >> 1) * 64, wn = (w & 1) * 64; // 2x2 warp grid, 64x64

    const int lr = t >> 3;          // chunk row (0..15)
    const int lc = (t & 7) * 8;     // chunk col (elems)

    const int a_row = wm + (lane & 15);
    const int a_col = (lane >> 4) * 8;
    const int b_row = wn + (lane & 7) + ((lane >> 4) << 3);
    const int b_col = ((lane >> 3) & 1) * 8;

    float acc[4][8][4] = {};

    auto issue = [&](int j) {
        const int st = j % NSTG;
        const int k0 = j * BK;
        #pragma unroll
        for (int i = 0; i < 8; i++) {
            int r = lr + i * 16;
            u32 da = (u32)__cvta_generic_to_shared(&Asm[st * BM * LDSW + r * LDSW + lc]);
            const bf16* ga = Ab + (size_t)r * lda + k0 + lc;
            asm volatile("cp.async.cg.shared.global [%0], [%1], 16;\n" :: "r"(da), "l"(ga));
            u32 db = (u32)__cvta_generic_to_shared(&Bsm[st * BN * LDSW + r * LDSW + lc]);
            const bf16* gbp = Bb + (size_t)r * ldb + k0 + lc;
            asm volatile("cp.async.cg.shared.global [%0], [%1], 16;\n" :: "r"(db), "l"(gbp));
        }
    };

    const int KT = K / BK;
    issue(0);
    asm volatile("cp.async.commit_group;\n");
    if (1 < KT) issue(1);
    asm volatile("cp.async.commit_group;\n");

    for (int kt = 0; kt < KT; kt++) {
        asm volatile("cp.async.wait_group 1;\n");
        __syncthreads();
        // early prefetch of stage kt+2 (overwrites stage read at kt-1; safe past barrier)
        if (kt + 2 < KT) issue(kt + 2);
        asm volatile("cp.async.commit_group;\n");

        const int st = kt % NSTG;
        const bf16* as = Asm + st * BM * LDSW;
        const bf16* bs = Bsm + st * BN * LDSW;

        u32 afrag[2][4][4], bfrag[2][8][2];

        auto load_frags = [&](int ks, int buf) {
            const int colA = ks * 16 + a_col;
            const int colB = ks * 16 + b_col;
            #pragma unroll
            for (int mt = 0; mt < 4; mt++) {
                u32 addr = (u32)__cvta_generic_to_shared(&as[(a_row + mt * 16) * LDSW + colA]);
                asm volatile("ldmatrix.sync.aligned.m8n8.x4.shared.b16 {%0,%1,%2,%3}, [%4];\n"
                    : "=r"(afrag[buf][mt][0]), "=r"(afrag[buf][mt][1]),
                      "=r"(afrag[buf][mt][2]), "=r"(afrag[buf][mt][3])
                    : "r"(addr));
            }
            #pragma unroll
            for (int np = 0; np < 4; np++) {
                u32 addr = (u32)__cvta_generic_to_shared(&bs[(b_row + np * 16) * LDSW + colB]);
                u32 bt0, bt1, bt2, bt3;
                asm volatile("ldmatrix.sync.aligned.m8n8.x4.shared.b16 {%0,%1,%2,%3}, [%4];\n"
                    : "=r"(bt0), "=r"(bt1), "=r"(bt2), "=r"(bt3) : "r"(addr));
                bfrag[buf][np * 2][0]     = bt0;
                bfrag[buf][np * 2][1]     = bt1;
                bfrag[buf][np * 2 + 1][0] = bt2;
                bfrag[buf][np * 2 + 1][1] = bt3;
            }
        };

        load_frags(0, 0);
        #pragma unroll
        for (int ks = 0; ks < 4; ks++) {
            const int cur = ks & 1;
            if (ks < 3) load_frags(ks + 1, cur ^ 1);
            #pragma unroll
            for (int mt = 0; mt < 4; mt++)
                #pragma unroll
                for (int nt = 0; nt < 8; nt++)
                    asm volatile(
                        "mma.sync.aligned.m16n8k16.row.col.f32.bf16.bf16.f32 "
                        "{%0,%1,%2,%3}, {%4,%5,%6,%7}, {%8,%9}, {%0,%1,%2,%3};\n"
                        : "+f"(acc[mt][nt][0]), "+f"(acc[mt][nt][1]),
                          "+f"(acc[mt][nt][2]), "+f"(acc[mt][nt][3])
                        : "r"(afrag[cur][mt][0]), "r"(afrag[cur][mt][1]),
                          "r"(afrag[cur][mt][2]), "r"(afrag[cur][mt][3]),
                          "r"(bfrag[cur][nt][0]), "r"(bfrag[cur][nt][1]));
        }
    }

    // --- epilogue ---
    const int m0 = blockIdx.y * BM + wm, n0 = blockIdx.x * BN + wn;
    OutT* Cb = C + (size_t)bz * sC;
    const float* Rb = resid ? resid + (size_t)bz * sR : nullptr;
    #pragma unroll
    for (int mt = 0; mt < 4; mt++) {
        #pragma unroll
        for (int hh = 0; hh < 2; hh++) {
            int m = m0 + mt * 16 + (lane >> 2) + hh * 8;
            float bm = bias_m ? bias_m[m] : 0.f;
            #pragma unroll
            for (int nt = 0; nt < 8; nt++) {
                int n = n0 + nt * 8 + (lane & 3) * 2;
                float v0 = alpha * acc[mt][nt][hh * 2 + 0] + bm;
                float v1 = alpha * acc[mt][nt][hh * 2 + 1] + bm;
                if (bias_n) { v0 += bias_n[n]; v1 += bias_n[n + 1]; }
                size_t idx = (size_t)m * N + n;
                if (Rb) { v0 += Rb[idx]; v1 += Rb[idx + 1]; }
                store2(&Cb[idx], v0, v1);
            }
        }
    }
}

// ---------------- row softmax: one warp per row, bf16 in/out ----------------
__global__ void __launch_bounds__(256)
softmax_kernel(const bf16* __restrict__ s, bf16* __restrict__ p) {
    const int warp = threadIdx.x >> 5, lane = threadIdx.x & 31;
    const size_t row = (size_t)blockIdx.x * 8 + warp;
    const bf16* sp = s + row * NTOK;
    bf16* pp = p + row * NTOK;

    uint4 raw[4];
    #pragma unroll
    for (int i = 0; i < 4; i++)
        raw[i] = reinterpret_cast<const uint4*>(sp)[lane + 32 * i];

    float v[32];
    #pragma unroll
    for (int i = 0; i < 4; i++) {
        const bf16* e = reinterpret_cast<const bf16*>(&raw[i]);
        #pragma unroll
        for (int j = 0; j < 8; j++) v[i * 8 + j] = __bfloat162float(e[j]);
    }

    float mx = -1e30f;
    #pragma unroll
    for (int i = 0; i < 32; i++) mx = fmaxf(mx, v[i]);
    #pragma unroll
    for (int o = 16; o > 0; o >>= 1)
        mx = fmaxf(mx, __shfl_xor_sync(0xffffffffu, mx, o));

    float sum = 0.f;
    #pragma unroll
    for (int i = 0; i < 32; i++) { v[i] = __expf(v[i] - mx); sum += v[i]; }
    #pragma unroll
    for (int o = 16; o > 0; o >>= 1)
        sum += __shfl_xor_sync(0xffffffffu, sum, o);

    const float inv = __frcp_rn(sum);
    uint4 outw[4];
    #pragma unroll
    for (int i = 0; i < 4; i++) {
        bf16* e = reinterpret_cast<bf16*>(&outw[i]);
        #pragma unroll
        for (int j = 0; j < 8; j += 2) {
            __nv_bfloat162 pr = __floats2bfloat162_rn(v[i * 8 + j] * inv, v[i * 8 + j + 1] * inv);
            *reinterpret_cast<__nv_bfloat162*>(&e[j]) = pr;
        }
        reinterpret_cast<uint4*>(pp)[lane + 32 * i] = outw[i];
    }
}

extern "C" void kernel_launch(void* const* d_in, const int* in_sizes, int n_in,
                              void* d_out, int out_size) {
    (void)in_sizes; (void)n_in; (void)out_size;
    const float* x  = (const float*)d_in[0];
    const float* gw = (const float*)d_in[1];
    const float* gb = (const float*)d_in[2];
    const float* wq = (const float*)d_in[3];
    const float* bq = (const float*)d_in[4];
    const float* wk = (const float*)d_in[5];
    const float* bk = (const float*)d_in[6];
    const float* wv = (const float*)d_in[7];
    const float* bv = (const float*)d_in[8];
    const float* wp = (const float*)d_in[9];
    const float* bp = (const float*)d_in[10];
    float* out = (float*)d_out;

    bf16 *h, *qk, *vt, *s, *p, *o, *w;
    float *bqk;
    cudaGetSymbolAddress((void**)&h,   g_h);
    cudaGetSymbolAddress((void**)&qk,  g_qk);
    cudaGetSymbolAddress((void**)&vt,  g_vt);
    cudaGetSymbolAddress((void**)&s,   g_s);
    cudaGetSymbolAddress((void**)&p,   g_p);
    cudaGetSymbolAddress((void**)&o,   g_o);
    cudaGetSymbolAddress((void**)&w,   g_w);
    cudaGetSymbolAddress((void**)&bqk, g_bqk);

    cudaFuncSetAttribute(mma_gemm<bf16>,  cudaFuncAttributeMaxDynamicSharedMemorySize, GEMM_SMEM);
    cudaFuncSetAttribute(mma_gemm<float>, cudaFuncAttributeMaxDynamicSharedMemorySize, GEMM_SMEM);

    const long NC  = (long)NTOK * CH;        // stride of [t][c] tensors
    const long NC2 = (long)NTOK * 2 * CH;    // stride of fused qk
    const long SS  = (long)NTOK * NTOK;

    convw_kernel<<<(CH * CH + 255) / 256, 256>>>(wq, wk, wv, wp, bq, bk, w, bqk);
    gn_kernel<<<BATCH * NGRP, 256>>>(x, gw, gb, h);

    // fused QK: qk[t][0:512]=q, [512:1024]=k. M=NTOK, N=2CH, K=CH
    dim3 gQK(2 * CH / BN, NTOK / BM, BATCH);  // (8,8,32)
    mma_gemm<bf16><<<gQK, NTHR, GEMM_SMEM>>>(h, w, qk, CH, CH, CH, 2 * CH,
                                             NC, 0, NC2,
                                             1.f, nullptr, bqk, nullptr, 0);
    // vt[c][t]: M=CH, N=NTOK, K=CH (bias on m)
    dim3 gV(NTOK / BN, CH / BM, BATCH);       // (8,4,32)
    mma_gemm<bf16><<<gV, NTHR, GEMM_SMEM>>>(w + 2 * CH * CH, h, vt, CH, CH, CH, NTOK,
                                            0, NC, NC,
                                            1.f, bv, nullptr, nullptr, 0);

    // scores S[tq][tk] (bf16): A=q (ld 1024), B=k (ld 1024), K=CH
    dim3 gS(NTOK / BN, NTOK / BM, BATCH);     // (8,8,32)
    const float scale = 1.0f / sqrtf((float)CH);
    mma_gemm<bf16><<<gS, NTHR, GEMM_SMEM>>>(qk, qk + CH, s, CH, 2 * CH, 2 * CH, NTOK,
                                            NC2, NC2, SS,
                                            scale, nullptr, nullptr, nullptr, 0);

    softmax_kernel<<<BATCH * NTOK / 8, 256>>>(s, p);

    // o[tq][c] = P . vt : M=NTOK, N=CH, K=NTOK
    dim3 gO(CH / BN, NTOK / BM, BATCH);       // (4,8,32)
    mma_gemm<bf16><<<gO, NTHR, GEMM_SMEM>>>(p, vt, o, NTOK, NTOK, NTOK, CH,
                                            SS, NC, NC,
                                            1.f, nullptr, nullptr, nullptr, 0);

    // out[c][t] = x + wp . o + bp : M=CH, N=NTOK, K=CH
    dim3 gP(NTOK / BN, CH / BM, BATCH);       // (8,4,32)
    mma_gemm<float><<<gP, NTHR, GEMM_SMEM>>>(w + 3 * CH * CH, o, out, CH, CH, CH, NTOK,
                                             0, NC, NC,
                                             1.f, bp, nullptr, x, NC);
}

// round 15
// speedup vs baseline: 1.1082x; 1.1082x over previous
#include <cuda_runtime.h>
#include <cuda_bf16.h>
#include <stdint.h>
#include <math.h>

#define BATCH 32
#define CH    512
#define NTOK  1024
#define NGRP  32
#define CPG   16

typedef __nv_bfloat16 bf16;
typedef unsigned int u32;

// ---------------- scratch (device globals) ----------------
__device__ bf16  g_h  [(size_t)BATCH * NTOK * CH];       // [b][t][c]
__device__ bf16  g_qk [(size_t)BATCH * NTOK * 2 * CH];   // [b][t][q|k]
__device__ bf16  g_vt [(size_t)BATCH * CH * NTOK];       // [b][c][t]
__device__ bf16  g_s  [(size_t)BATCH * NTOK * NTOK];     // scores bf16
__device__ bf16  g_p  [(size_t)BATCH * NTOK * NTOK];     // probs bf16
__device__ bf16  g_o  [(size_t)BATCH * NTOK * CH];       // [b][t][c]
__device__ bf16  g_w  [4 * CH * CH];                     // wq|wk|wv|wp bf16
__device__ float g_bqk[2 * CH];                          // bq|bk

// ---------------- weight fp32 -> bf16 (+ fused qk bias) ----------------
__global__ void convw_kernel(const float* __restrict__ wq, const float* __restrict__ wk,
                             const float* __restrict__ wv, const float* __restrict__ wp,
                             const float* __restrict__ bq, const float* __restrict__ bk,
                             bf16* __restrict__ w, float* __restrict__ bqk) {
    int i = blockIdx.x * 256 + threadIdx.x;
    if (i < CH * CH) {
        w[i]               = __float2bfloat16(wq[i]);
        w[CH * CH + i]     = __float2bfloat16(wk[i]);
        w[2 * CH * CH + i] = __float2bfloat16(wv[i]);
        w[3 * CH * CH + i] = __float2bfloat16(wp[i]);
    }
    if (i < CH) {
        bqk[i]      = bq[i];
        bqk[CH + i] = bk[i];
    }
}

// ---------------- GroupNorm: single pass, fp32 stats, bf16 out --------------
__global__ void __launch_bounds__(256)
gn_kernel(const float* __restrict__ x,
          const float* __restrict__ gw,
          const float* __restrict__ gb,
          bf16* __restrict__ h) {
    const int bg = blockIdx.x;
    const int b = bg / NGRP, g = bg % NGRP;
    const int n = CPG * NTOK;
    const size_t base = (size_t)bg * n;
    const int t = threadIdx.x;

    float v[4][CPG];
    float s = 0.f, ss = 0.f;
    #pragma unroll
    for (int j = 0; j < 4; j++) {
        const int tok = t + 256 * j;
        #pragma unroll
        for (int i = 0; i < CPG; i++) {
            float val = x[base + (size_t)i * NTOK + tok];
            v[j][i] = val; s += val; ss += val * val;
        }
    }
    __shared__ float rs[256], rq[256];
    rs[t] = s; rq[t] = ss;
    __syncthreads();
    for (int o = 128; o > 0; o >>= 1) {
        if (t < o) { rs[t] += rs[t + o]; rq[t] += rq[t + o]; }
        __syncthreads();
    }
    const float mean = rs[0] * (1.0f / n);
    const float var  = rq[0] * (1.0f / n) - mean * mean;
    const float rstd = rsqrtf(var + 1e-5f);

    float a[CPG], c[CPG];
    #pragma unroll
    for (int i = 0; i < CPG; i++) {
        a[i] = rstd * gw[g * CPG + i];
        c[i] = gb[g * CPG + i] - mean * a[i];
    }
    #pragma unroll
    for (int j = 0; j < 4; j++) {
        const int tok = t + 256 * j;
        bf16 buf[CPG];
        #pragma unroll
        for (int i = 0; i < CPG; i++)
            buf[i] = __float2bfloat16(v[j][i] * a[i] + c[i]);
        size_t ho = ((size_t)(b * NTOK + tok)) * CH + g * CPG;
        uint4* dst = reinterpret_cast<uint4*>(&h[ho]);
        const uint4* src = reinterpret_cast<const uint4*>(buf);
        dst[0] = src[0];
        dst[1] = src[1];
    }
}

// ---------------- epilogue store helpers ----------------
__device__ __forceinline__ void store2(float* p, float v0, float v1) {
    *reinterpret_cast<float2*>(p) = make_float2(v0, v1);
}
__device__ __forceinline__ void store2(bf16* p, float v0, float v1) {
    *reinterpret_cast<__nv_bfloat162*>(p) = __floats2bfloat162_rn(v0, v1);
}

// ---------------- bf16 TN GEMM: 128x128 tile, 128 thr, 64x64 warp tile ------
// C[m][n] = alpha * sum_k A[m][k]*B[n][k] (+bias_m[m]) (+bias_n[n]) (+resid)
// A rows at LDA (compile-time), B rows at LDB; C: [M][N] (ld=N).
// BK=64, 3-stage cp.async ring (commit inside issue), one syncthreads/k-tile.
// Last iteration uses wait_group 0 (race-free).
#define BM 128
#define BN 128
#define BK 64
#define LDSW 72  // BK + 8 pad (conflict-free ldmatrix)
#define NSTG 3
#define NTHR 128
#define GEMM_SMEM ((BM + BN) * LDSW * NSTG * 2)   // 110592 bytes

template<typename OutT, int LDA, int LDB>
__global__ void __launch_bounds__(NTHR, 2)
mma_gemm(const bf16* __restrict__ A, const bf16* __restrict__ B, OutT* __restrict__ C,
         int K, int N, long sA, long sB, long sC,
         float alpha, const float* __restrict__ bias_m, const float* __restrict__ bias_n,
         const float* __restrict__ resid, long sR) {
    extern __shared__ bf16 sm[];
    bf16* Asm = sm;
    bf16* Bsm = sm + NSTG * BM * LDSW;

    const int bz = blockIdx.z;
    const bf16* Ab = A + (size_t)bz * sA + (size_t)(blockIdx.y * BM) * LDA;
    const bf16* Bb = B + (size_t)bz * sB + (size_t)(blockIdx.x * BN) * LDB;

    const int t = threadIdx.x;
    const int lane = t & 31, w = t >> 5;             // 4 warps
    const int wm = (w >> 1) * 64, wn = (w & 1) * 64; // 2x2 warp grid, 64x64

    const int lr = t >> 3;          // chunk row (0..15)
    const int lc = (t & 7) * 8;     // chunk col (elems)

    const int a_row = wm + (lane & 15);
    const int a_col = (lane >> 4) * 8;
    const int b_row = wn + (lane & 7) + ((lane >> 4) << 3);
    const int b_col = ((lane >> 3) & 1) * 8;

    float acc[4][8][4] = {};

    auto issue = [&](int j) {
        const int st = j % NSTG;
        const int k0 = j * BK;
        #pragma unroll
        for (int i = 0; i < 8; i++) {
            int r = lr + i * 16;
            u32 da = (u32)__cvta_generic_to_shared(&Asm[st * BM * LDSW + r * LDSW + lc]);
            const bf16* ga = Ab + (size_t)r * LDA + k0 + lc;
            asm volatile("cp.async.cg.shared.global [%0], [%1], 16;\n" :: "r"(da), "l"(ga));
            u32 db = (u32)__cvta_generic_to_shared(&Bsm[st * BN * LDSW + r * LDSW + lc]);
            const bf16* gbp = Bb + (size_t)r * LDB + k0 + lc;
            asm volatile("cp.async.cg.shared.global [%0], [%1], 16;\n" :: "r"(db), "l"(gbp));
        }
        asm volatile("cp.async.commit_group;\n");
    };

    const int KT = K / BK;
    issue(0);
    if (1 < KT) issue(1);

    for (int kt = 0; kt < KT; kt++) {
        if (kt + 1 < KT) {
            asm volatile("cp.async.wait_group 1;\n");
        } else {
            asm volatile("cp.async.wait_group 0;\n");
        }
        __syncthreads();
        const int st = kt % NSTG;
        const bf16* as = Asm + st * BM * LDSW;
        const bf16* bs = Bsm + st * BN * LDSW;

        u32 afrag[2][4][4], bfrag[2][8][2];

        auto load_frags = [&](int ks, int buf) {
            const int colA = ks * 16 + a_col;
            const int colB = ks * 16 + b_col;
            #pragma unroll
            for (int mt = 0; mt < 4; mt++) {
                u32 addr = (u32)__cvta_generic_to_shared(&as[(a_row + mt * 16) * LDSW + colA]);
                asm volatile("ldmatrix.sync.aligned.m8n8.x4.shared.b16 {%0,%1,%2,%3}, [%4];\n"
                    : "=r"(afrag[buf][mt][0]), "=r"(afrag[buf][mt][1]),
                      "=r"(afrag[buf][mt][2]), "=r"(afrag[buf][mt][3])
                    : "r"(addr));
            }
            #pragma unroll
            for (int np = 0; np < 4; np++) {
                u32 addr = (u32)__cvta_generic_to_shared(&bs[(b_row + np * 16) * LDSW + colB]);
                u32 bt0, bt1, bt2, bt3;
                asm volatile("ldmatrix.sync.aligned.m8n8.x4.shared.b16 {%0,%1,%2,%3}, [%4];\n"
                    : "=r"(bt0), "=r"(bt1), "=r"(bt2), "=r"(bt3) : "r"(addr));
                bfrag[buf][np * 2][0]     = bt0;
                bfrag[buf][np * 2][1]     = bt1;
                bfrag[buf][np * 2 + 1][0] = bt2;
                bfrag[buf][np * 2 + 1][1] = bt3;
            }
        };

        load_frags(0, 0);
        #pragma unroll
        for (int ks = 0; ks < 4; ks++) {
            const int cur = ks & 1;
            if (ks < 3) load_frags(ks + 1, cur ^ 1);
            #pragma unroll
            for (int mt = 0; mt < 4; mt++)
                #pragma unroll
                for (int nt = 0; nt < 8; nt++)
                    asm volatile(
                        "mma.sync.aligned.m16n8k16.row.col.f32.bf16.bf16.f32 "
                        "{%0,%1,%2,%3}, {%4,%5,%6,%7}, {%8,%9}, {%0,%1,%2,%3};\n"
                        : "+f"(acc[mt][nt][0]), "+f"(acc[mt][nt][1]),
                          "+f"(acc[mt][nt][2]), "+f"(acc[mt][nt][3])
                        : "r"(afrag[cur][mt][0]), "r"(afrag[cur][mt][1]),
                          "r"(afrag[cur][mt][2]), "r"(afrag[cur][mt][3]),
                          "r"(bfrag[cur][nt][0]), "r"(bfrag[cur][nt][1]));
        }
        if (kt + 2 < KT) issue(kt + 2);
    }

    // --- epilogue ---
    const int m0 = blockIdx.y * BM + wm, n0 = blockIdx.x * BN + wn;
    OutT* Cb = C + (size_t)bz * sC;
    const float* Rb = resid ? resid + (size_t)bz * sR : nullptr;
    #pragma unroll
    for (int mt = 0; mt < 4; mt++) {
        #pragma unroll
        for (int hh = 0; hh < 2; hh++) {
            int m = m0 + mt * 16 + (lane >> 2) + hh * 8;
            float bm = bias_m ? bias_m[m] : 0.f;
            #pragma unroll
            for (int nt = 0; nt < 8; nt++) {
                int n = n0 + nt * 8 + (lane & 3) * 2;
                float v0 = alpha * acc[mt][nt][hh * 2 + 0] + bm;
                float v1 = alpha * acc[mt][nt][hh * 2 + 1] + bm;
                if (bias_n) { v0 += bias_n[n]; v1 += bias_n[n + 1]; }
                size_t idx = (size_t)m * N + n;
                if (Rb) { v0 += Rb[idx]; v1 += Rb[idx + 1]; }
                store2(&Cb[idx], v0, v1);
            }
        }
    }
}

// ---------------- row softmax: one warp per row, bf16 in/out ----------------
__global__ void __launch_bounds__(256)
softmax_kernel(const bf16* __restrict__ s, bf16* __restrict__ p) {
    const int warp = threadIdx.x >> 5, lane = threadIdx.x & 31;
    const size_t row = (size_t)blockIdx.x * 8 + warp;
    const bf16* sp = s + row * NTOK;
    bf16* pp = p + row * NTOK;

    uint4 raw[4];
    #pragma unroll
    for (int i = 0; i < 4; i++)
        raw[i] = reinterpret_cast<const uint4*>(sp)[lane + 32 * i];

    float v[32];
    #pragma unroll
    for (int i = 0; i < 4; i++) {
        const bf16* e = reinterpret_cast<const bf16*>(&raw[i]);
        #pragma unroll
        for (int j = 0; j < 8; j++) v[i * 8 + j] = __bfloat162float(e[j]);
    }

    float mx = -1e30f;
    #pragma unroll
    for (int i = 0; i < 32; i++) mx = fmaxf(mx, v[i]);
    #pragma unroll
    for (int o = 16; o > 0; o >>= 1)
        mx = fmaxf(mx, __shfl_xor_sync(0xffffffffu, mx, o));

    float sum = 0.f;
    #pragma unroll
    for (int i = 0; i < 32; i++) { v[i] = __expf(v[i] - mx); sum += v[i]; }
    #pragma unroll
    for (int o = 16; o > 0; o >>= 1)
        sum += __shfl_xor_sync(0xffffffffu, sum, o);

    const float inv = __frcp_rn(sum);
    uint4 outw[4];
    #pragma unroll
    for (int i = 0; i < 4; i++) {
        bf16* e = reinterpret_cast<bf16*>(&outw[i]);
        #pragma unroll
        for (int j = 0; j < 8; j += 2) {
            __nv_bfloat162 pr = __floats2bfloat162_rn(v[i * 8 + j] * inv, v[i * 8 + j + 1] * inv);
            *reinterpret_cast<__nv_bfloat162*>(&e[j]) = pr;
        }
        reinterpret_cast<uint4*>(pp)[lane + 32 * i] = outw[i];
    }
}

extern "C" void kernel_launch(void* const* d_in, const int* in_sizes, int n_in,
                              void* d_out, int out_size) {
    (void)in_sizes; (void)n_in; (void)out_size;
    const float* x  = (const float*)d_in[0];
    const float* gw = (const float*)d_in[1];
    const float* gb = (const float*)d_in[2];
    const float* wq = (const float*)d_in[3];
    const float* bq = (const float*)d_in[4];
    const float* wk = (const float*)d_in[5];
    const float* bk = (const float*)d_in[6];
    const float* wv = (const float*)d_in[7];
    const float* bv = (const float*)d_in[8];
    const float* wp = (const float*)d_in[9];
    const float* bp = (const float*)d_in[10];
    float* out = (float*)d_out;

    bf16 *h, *qk, *vt, *s, *p, *o, *w;
    float *bqk;
    cudaGetSymbolAddress((void**)&h,   g_h);
    cudaGetSymbolAddress((void**)&qk,  g_qk);
    cudaGetSymbolAddress((void**)&vt,  g_vt);
    cudaGetSymbolAddress((void**)&s,   g_s);
    cudaGetSymbolAddress((void**)&p,   g_p);
    cudaGetSymbolAddress((void**)&o,   g_o);
    cudaGetSymbolAddress((void**)&w,   g_w);
    cudaGetSymbolAddress((void**)&bqk, g_bqk);

    cudaFuncSetAttribute((const void*)mma_gemm<bf16, CH, CH>,
                         cudaFuncAttributeMaxDynamicSharedMemorySize, GEMM_SMEM);
    cudaFuncSetAttribute((const void*)mma_gemm<bf16, 2 * CH, 2 * CH>,
                         cudaFuncAttributeMaxDynamicSharedMemorySize, GEMM_SMEM);
    cudaFuncSetAttribute((const void*)mma_gemm<bf16, NTOK, NTOK>,
                         cudaFuncAttributeMaxDynamicSharedMemorySize, GEMM_SMEM);
    cudaFuncSetAttribute((const void*)mma_gemm<float, CH, CH>,
                         cudaFuncAttributeMaxDynamicSharedMemorySize, GEMM_SMEM);

    const long NC  = (long)NTOK * CH;        // stride of [t][c] tensors
    const long NC2 = (long)NTOK * 2 * CH;    // stride of fused qk
    const long SS  = (long)NTOK * NTOK;

    convw_kernel<<<(CH * CH + 255) / 256, 256>>>(wq, wk, wv, wp, bq, bk, w, bqk);
    gn_kernel<<<BATCH * NGRP, 256>>>(x, gw, gb, h);

    // fused QK: qk[t][0:512]=q, [512:1024]=k. M=NTOK, N=2CH, K=CH
    dim3 gQK(2 * CH / BN, NTOK / BM, BATCH);  // (8,8,32)
    mma_gemm<bf16, CH, CH><<<gQK, NTHR, GEMM_SMEM>>>(
        h, w, qk, CH, 2 * CH, NC, 0, NC2, 1.f, nullptr, bqk, nullptr, 0);

    // vt[c][t]: M=CH, N=NTOK, K=CH (bias on m)
    dim3 gV(NTOK / BN, CH / BM, BATCH);       // (8,4,32)
    mma_gemm<bf16, CH, CH><<<gV, NTHR, GEMM_SMEM>>>(
        w + 2 * CH * CH, h, vt, CH, NTOK, 0, NC, NC, 1.f, bv, nullptr, nullptr, 0);

    // scores S[tq][tk] (bf16): A=q, B=k inside fused qk (ld 1024), K=CH
    dim3 gS(NTOK / BN, NTOK / BM, BATCH);     // (8,8,32)
    const float scale = 1.0f / sqrtf((float)CH);
    mma_gemm<bf16, 2 * CH, 2 * CH><<<gS, NTHR, GEMM_SMEM>>>(
        qk, qk + CH, s, CH, NTOK, NC2, NC2, SS, scale, nullptr, nullptr, nullptr, 0);

    softmax_kernel<<<BATCH * NTOK / 8, 256>>>(s, p);

    // o[tq][c] = P . vt : M=NTOK, N=CH, K=NTOK
    dim3 gO(CH / BN, NTOK / BM, BATCH);       // (4,8,32)
    mma_gemm<bf16, NTOK, NTOK><<<gO, NTHR, GEMM_SMEM>>>(
        p, vt, o, NTOK, CH, SS, NC, NC, 1.f, nullptr, nullptr, nullptr, 0);

    // out[c][t] = x + wp . o + bp : M=CH, N=NTOK, K=CH
    dim3 gP(NTOK / BN, CH / BM, BATCH);       // (8,4,32)
    mma_gemm<float, CH, CH><<<gP, NTHR, GEMM_SMEM>>>(
        w + 3 * CH * CH, o, out, CH, NTOK, 0, NC, NC, 1.f, bp, nullptr, x, NC);
}